// round 1
// baseline (speedup 1.0000x reference)
#include <cuda_runtime.h>
#include <math.h>

// Problem constants
#define Bv 2
#define Tv 8
#define Nv 576
#define Cv 1024
#define Hv 16
#define HDv 64
#define TNv (Tv * Nv)       // 4608
#define Mrows (Bv * TNv)    // 9216

// Scratch (device globals — no runtime allocation allowed)
__device__ float g_q[(size_t)Mrows * Cv];
__device__ float g_k[(size_t)Mrows * Cv];
__device__ float g_v[(size_t)Mrows * Cv];
__device__ float g_o[(size_t)Mrows * Cv];

// ---------------------------------------------------------------------------
// NT GEMM: C[m,n] = sum_k A[m,k] * W[n,k] (+ bias[n])
// A: [Mrows, 1024], W: [1024, 1024], both row-major, K contiguous.
// 128x128 tile, BK=8, 256 threads, 8x8 per thread (2x2 blocks of 4x4).
// ---------------------------------------------------------------------------
__global__ __launch_bounds__(256) void gemm_nt(
    const float* __restrict__ A, const float* __restrict__ W,
    float* __restrict__ Cout, const float* __restrict__ bias)
{
    __shared__ float As[8][132];
    __shared__ float Bs[8][132];

    const int t  = threadIdx.x;
    const int tx = t & 15;
    const int ty = t >> 4;
    const int m0 = blockIdx.y * 128;
    const int n0 = blockIdx.x * 128;

    const int lrow = t >> 1;        // 0..127
    const int lk4  = (t & 1) * 4;   // 0 or 4

    float acc[8][8];
#pragma unroll
    for (int i = 0; i < 8; i++)
#pragma unroll
        for (int j = 0; j < 8; j++) acc[i][j] = 0.0f;

    const float* Aptr = A + (size_t)(m0 + lrow) * Cv + lk4;
    const float* Wptr = W + (size_t)(n0 + lrow) * Cv + lk4;

    for (int kt = 0; kt < Cv; kt += 8) {
        float4 av = *(const float4*)(Aptr + kt);
        float4 wv = *(const float4*)(Wptr + kt);
        __syncthreads();
        As[lk4 + 0][lrow] = av.x;
        As[lk4 + 1][lrow] = av.y;
        As[lk4 + 2][lrow] = av.z;
        As[lk4 + 3][lrow] = av.w;
        Bs[lk4 + 0][lrow] = wv.x;
        Bs[lk4 + 1][lrow] = wv.y;
        Bs[lk4 + 2][lrow] = wv.z;
        Bs[lk4 + 3][lrow] = wv.w;
        __syncthreads();
#pragma unroll
        for (int kk = 0; kk < 8; kk++) {
            float4 a0 = *(const float4*)&As[kk][ty * 4];
            float4 a1 = *(const float4*)&As[kk][64 + ty * 4];
            float4 b0 = *(const float4*)&Bs[kk][tx * 4];
            float4 b1 = *(const float4*)&Bs[kk][64 + tx * 4];
            float a[8] = {a0.x, a0.y, a0.z, a0.w, a1.x, a1.y, a1.z, a1.w};
            float b[8] = {b0.x, b0.y, b0.z, b0.w, b1.x, b1.y, b1.z, b1.w};
#pragma unroll
            for (int i = 0; i < 8; i++)
#pragma unroll
                for (int j = 0; j < 8; j++)
                    acc[i][j] = fmaf(a[i], b[j], acc[i][j]);
        }
    }

#pragma unroll
    for (int ii = 0; ii < 8; ii++) {
        int r = (ii < 4) ? (ty * 4 + ii) : (64 + ty * 4 + (ii - 4));
#pragma unroll
        for (int jj = 0; jj < 8; jj++) {
            int c = (jj < 4) ? (tx * 4 + jj) : (64 + tx * 4 + (jj - 4));
            float val = acc[ii][jj];
            if (bias) val += bias[n0 + c];
            Cout[(size_t)(m0 + r) * Cv + n0 + c] = val;
        }
    }
}

// ---------------------------------------------------------------------------
// RoPE (in-place on q and k, token-major [Mrows,1024] layout).
// pair (2i, 2i+1) within each head:
//   y0 = x0*cos[d]   - x1*sin[d]
//   y1 = x1*cos[d+1] + x0*sin[d+1]
// ---------------------------------------------------------------------------
__global__ __launch_bounds__(256) void rope_kernel(
    const float* __restrict__ fcos, const float* __restrict__ fsin)
{
    const long total = (long)Mrows * 512;   // pairs per array
    long gid = (long)blockIdx.x * blockDim.x + threadIdx.x;
    if (gid >= 2 * total) return;
    float* arr = (gid < total) ? g_q : g_k;
    long id = (gid < total) ? gid : (gid - total);

    int m = (int)(id / 512);
    int p = (int)(id % 512);
    int col = p * 2;
    int d = col & 63;          // position within head
    int s = m % TNv;           // freqs row

    float c0 = fcos[(size_t)s * HDv + d];
    float c1 = fcos[(size_t)s * HDv + d + 1];
    float s0 = fsin[(size_t)s * HDv + d];
    float s1 = fsin[(size_t)s * HDv + d + 1];

    float2 x = *(float2*)(arr + (size_t)m * Cv + col);
    float2 y;
    y.x = x.x * c0 - x.y * s0;
    y.y = x.y * c1 + x.x * s1;
    *(float2*)(arr + (size_t)m * Cv + col) = y;
}

// ---------------------------------------------------------------------------
// Flash-style cross-neighbor attention.
// Block = (b, h, t, 64-row q tile). 256 threads (16x16), online softmax over
// 18 key tiles of 64 (keys 0..575 from t_prev frame, 576..1151 from t_next).
// Writes O directly in token-major [Mrows,1024] layout (ready for out proj).
// ---------------------------------------------------------------------------
#define ATTN_SMEM_FLOATS (4 * 64 * 68)
__global__ __launch_bounds__(256) void attn_kernel()
{
    extern __shared__ float sm[];
    float* Qt = sm;                 // [d][row]  (64 x 68)
    float* Kt = sm + 64 * 68;       // [d][key]
    float* Vs = sm + 2 * 64 * 68;   // [key][d]
    float* Ps = sm + 3 * 64 * 68;   // [key][qrow]

    const int bx = blockIdx.x;
    const int nb = bx % 9;
    const int tt = (bx / 9) % Tv;
    const int h  = (bx / (9 * Tv)) % Hv;
    const int b  = bx / (9 * Tv * Hv);
    const int tprev = (tt == 0) ? 1 : tt - 1;
    const int tnext = (tt == Tv - 1) ? Tv - 2 : tt + 1;

    const int tid  = threadIdx.x;
    const int tx   = tid & 15;
    const int ty   = tid >> 4;
    const int lrow = tid >> 2;       // 0..63 (token for tile loads)
    const int dc   = (tid & 3) * 16; // d-chunk start

    // Load Q tile, fold in softmax scale 1/sqrt(64)
    {
        const float* qbase =
            g_q + (size_t)(b * TNv + tt * Nv + nb * 64 + lrow) * Cv + h * HDv;
#pragma unroll
        for (int j = 0; j < 4; j++) {
            float4 v = *(const float4*)(qbase + dc + 4 * j);
            int d0 = dc + 4 * j;
            Qt[(d0 + 0) * 68 + lrow] = v.x * 0.125f;
            Qt[(d0 + 1) * 68 + lrow] = v.y * 0.125f;
            Qt[(d0 + 2) * 68 + lrow] = v.z * 0.125f;
            Qt[(d0 + 3) * 68 + lrow] = v.w * 0.125f;
        }
    }

    float mrow[4], lrow_sum[4], o[4][4];
#pragma unroll
    for (int i = 0; i < 4; i++) {
        mrow[i] = -INFINITY;
        lrow_sum[i] = 0.0f;
#pragma unroll
        for (int j = 0; j < 4; j++) o[i][j] = 0.0f;
    }

    for (int kt = 0; kt < 18; kt++) {
        const int tsrc = (kt < 9) ? tprev : tnext;
        const int nk0  = (kt % 9) * 64;
        const size_t tok = (size_t)(b * TNv + tsrc * Nv + nk0 + lrow);
        const float* kbase = g_k + tok * Cv + h * HDv + dc;
        const float* vbase = g_v + tok * Cv + h * HDv + dc;

        __syncthreads();   // prior tile's reads of Kt/Vs/Ps complete
#pragma unroll
        for (int j = 0; j < 4; j++) {
            float4 kv = *(const float4*)(kbase + 4 * j);
            float4 vv = *(const float4*)(vbase + 4 * j);
            int d0 = dc + 4 * j;
            Kt[(d0 + 0) * 68 + lrow] = kv.x;
            Kt[(d0 + 1) * 68 + lrow] = kv.y;
            Kt[(d0 + 2) * 68 + lrow] = kv.z;
            Kt[(d0 + 3) * 68 + lrow] = kv.w;
            *(float4*)&Vs[lrow * 68 + d0] = vv;
        }
        __syncthreads();

        // S = Q @ K^T  (rows ty*4+i, keys tx*4+j)
        float s[4][4];
#pragma unroll
        for (int i = 0; i < 4; i++)
#pragma unroll
            for (int j = 0; j < 4; j++) s[i][j] = 0.0f;
#pragma unroll
        for (int d = 0; d < 64; d++) {
            float4 a = *(const float4*)&Qt[d * 68 + ty * 4];
            float4 bb = *(const float4*)&Kt[d * 68 + tx * 4];
            float av[4] = {a.x, a.y, a.z, a.w};
            float bv[4] = {bb.x, bb.y, bb.z, bb.w};
#pragma unroll
            for (int i = 0; i < 4; i++)
#pragma unroll
                for (int j = 0; j < 4; j++)
                    s[i][j] = fmaf(av[i], bv[j], s[i][j]);
        }

        // online softmax update
#pragma unroll
        for (int i = 0; i < 4; i++) {
            float mx = fmaxf(fmaxf(s[i][0], s[i][1]), fmaxf(s[i][2], s[i][3]));
#pragma unroll
            for (int off = 1; off < 16; off <<= 1)
                mx = fmaxf(mx, __shfl_xor_sync(0xffffffffu, mx, off));
            float mnew = fmaxf(mrow[i], mx);
            float alpha = __expf(mrow[i] - mnew);
            mrow[i] = mnew;
            float rs = 0.0f;
#pragma unroll
            for (int j = 0; j < 4; j++) {
                float p = __expf(s[i][j] - mnew);
                s[i][j] = p;
                rs += p;
            }
#pragma unroll
            for (int off = 1; off < 16; off <<= 1)
                rs += __shfl_xor_sync(0xffffffffu, rs, off);
            lrow_sum[i] = lrow_sum[i] * alpha + rs;
#pragma unroll
            for (int j = 0; j < 4; j++) o[i][j] *= alpha;
            // stage P transposed: Ps[key][qrow]
#pragma unroll
            for (int j = 0; j < 4; j++)
                Ps[(tx * 4 + j) * 68 + ty * 4 + i] = s[i][j];
        }
        __syncthreads();

        // O += P @ V  (rows ty*4+i, d-cols tx*4+j)
#pragma unroll
        for (int key = 0; key < 64; key++) {
            float4 pv = *(const float4*)&Ps[key * 68 + ty * 4];
            float4 vv = *(const float4*)&Vs[key * 68 + tx * 4];
            float pa[4] = {pv.x, pv.y, pv.z, pv.w};
            float va[4] = {vv.x, vv.y, vv.z, vv.w};
#pragma unroll
            for (int i = 0; i < 4; i++)
#pragma unroll
                for (int j = 0; j < 4; j++)
                    o[i][j] = fmaf(pa[i], va[j], o[i][j]);
        }
    }

    // normalize + write (token-major layout, ready for output projection)
#pragma unroll
    for (int i = 0; i < 4; i++) {
        int r = ty * 4 + i;
        float inv = 1.0f / lrow_sum[i];
        float* obase =
            g_o + (size_t)(b * TNv + tt * Nv + nb * 64 + r) * Cv + h * HDv + tx * 4;
#pragma unroll
        for (int j = 0; j < 4; j++) obase[j] = o[i][j] * inv;
    }
}

// ---------------------------------------------------------------------------
// Launch
// ---------------------------------------------------------------------------
extern "C" void kernel_launch(void* const* d_in, const int* in_sizes, int n_in,
                              void* d_out, int out_size)
{
    (void)in_sizes; (void)n_in; (void)out_size;
    const float* img  = (const float*)d_in[0];
    const float* fcos = (const float*)d_in[1];
    const float* fsin = (const float*)d_in[2];
    const float* Wq   = (const float*)d_in[3];
    const float* Wk   = (const float*)d_in[4];
    const float* Wv   = (const float*)d_in[5];
    const float* Wo   = (const float*)d_in[6];
    const float* bo   = (const float*)d_in[7];
    float* out = (float*)d_out;

    float *q, *k, *v, *o;
    cudaGetSymbolAddress((void**)&q, g_q);
    cudaGetSymbolAddress((void**)&k, g_k);
    cudaGetSymbolAddress((void**)&v, g_v);
    cudaGetSymbolAddress((void**)&o, g_o);

    static_assert(ATTN_SMEM_FLOATS * sizeof(float) == 69632, "smem size");
    cudaFuncSetAttribute(attn_kernel,
                         cudaFuncAttributeMaxDynamicSharedMemorySize,
                         ATTN_SMEM_FLOATS * (int)sizeof(float));

    dim3 gblk(256);
    dim3 ggrid(Cv / 128, Mrows / 128);   // (8, 72)

    gemm_nt<<<ggrid, gblk>>>(img, Wq, q, nullptr);
    gemm_nt<<<ggrid, gblk>>>(img, Wk, k, nullptr);
    gemm_nt<<<ggrid, gblk>>>(img, Wv, v, nullptr);

    long pairs2 = 2L * Mrows * 512;
    int rblocks = (int)((pairs2 + 255) / 256);
    rope_kernel<<<rblocks, 256>>>(fcos, fsin);

    attn_kernel<<<Bv * Hv * Tv * 9, 256,
                  ATTN_SMEM_FLOATS * sizeof(float)>>>();

    gemm_nt<<<ggrid, gblk>>>(o, Wo, out, bo);
}

// round 3
// speedup vs baseline: 2.2337x; 2.2337x over previous
#include <cuda_runtime.h>
#include <math.h>

// Problem constants
#define Bv 2
#define Tv 8
#define Nv 576
#define Cv 1024
#define Hv 16
#define HDv 64
#define TNv (Tv * Nv)       // 4608
#define Mrows (Bv * TNv)    // 9216

// Scratch (device globals — no runtime allocation allowed)
__device__ float g_q[(size_t)Mrows * Cv];
__device__ float g_k[(size_t)Mrows * Cv];
__device__ float g_v[(size_t)Mrows * Cv];
__device__ float g_o[(size_t)Mrows * Cv];

// ---------------------------------------------------------------------------
// tf32 helpers
// ---------------------------------------------------------------------------
__device__ __forceinline__ unsigned tf32r(float x) {
    unsigned r;
    asm("cvt.rna.tf32.f32 %0, %1;" : "=r"(r) : "f"(x));
    return r;
}

__device__ __forceinline__ void mma8(float d[4], const unsigned a[4],
                                     const unsigned b[2]) {
    asm volatile(
        "mma.sync.aligned.m16n8k8.row.col.f32.tf32.tf32.f32 "
        "{%0,%1,%2,%3},{%4,%5,%6,%7},{%8,%9},{%0,%1,%2,%3};"
        : "+f"(d[0]), "+f"(d[1]), "+f"(d[2]), "+f"(d[3])
        : "r"(a[0]), "r"(a[1]), "r"(a[2]), "r"(a[3]), "r"(b[0]), "r"(b[1]));
}

// ---------------------------------------------------------------------------
// NT GEMM via tf32 mma: C[m,n] = sum_k A[m,k] * W[n,k] (+ bias[n])
// 128x128 block, BK=16, 8 warps (2m x 4n), warp tile 64x32.
// smem layout [k][col] stride 136, swizzle col ^ (((k>>2)&3)<<3):
// conflict-free for both the transposing stores and the fragment loads.
// ---------------------------------------------------------------------------
__global__ __launch_bounds__(256) void gemm_tf32(
    const float* __restrict__ A, const float* __restrict__ W,
    float* __restrict__ Cout, const float* __restrict__ bias)
{
    __shared__ unsigned As[16 * 136];
    __shared__ unsigned Bs[16 * 136];

    const int t = threadIdx.x;
    const int lane = t & 31;
    const int w = t >> 5;
    const int gid = lane >> 2, tig = lane & 3;
    const int wm = (w >> 2) * 64, wn = (w & 3) * 32;
    const int m0 = blockIdx.y * 128, n0 = blockIdx.x * 128;

    const int row0 = t >> 2;          // 0..63
    const int kq = (t & 3) * 4;       // 0,4,8,12
    const int cstS = (t & 3) << 3;    // ((k>>2)&3)<<3 for k = kq+jj

    const float* Ap0 = A + (size_t)(m0 + row0) * Cv + kq;
    const float* Ap1 = A + (size_t)(m0 + 64 + row0) * Cv + kq;
    const float* Wp0 = W + (size_t)(n0 + row0) * Cv + kq;
    const float* Wp1 = W + (size_t)(n0 + 64 + row0) * Cv + kq;

    float acc[4][4][4];
#pragma unroll
    for (int mt = 0; mt < 4; mt++)
#pragma unroll
        for (int nt = 0; nt < 4; nt++)
#pragma unroll
            for (int r = 0; r < 4; r++) acc[mt][nt][r] = 0.0f;

    float4 ra0 = *(const float4*)Ap0;
    float4 ra1 = *(const float4*)Ap1;
    float4 rb0 = *(const float4*)Wp0;
    float4 rb1 = *(const float4*)Wp1;

    for (int k0 = 0; k0 < Cv; k0 += 16) {
        __syncthreads();
        {
            float va0[4] = {ra0.x, ra0.y, ra0.z, ra0.w};
            float va1[4] = {ra1.x, ra1.y, ra1.z, ra1.w};
            float vb0[4] = {rb0.x, rb0.y, rb0.z, rb0.w};
            float vb1[4] = {rb1.x, rb1.y, rb1.z, rb1.w};
#pragma unroll
            for (int jj = 0; jj < 4; jj++) {
                int kr = (kq + jj) * 136;
                As[kr + (row0 ^ cstS)]        = tf32r(va0[jj]);
                As[kr + ((row0 + 64) ^ cstS)] = tf32r(va1[jj]);
                Bs[kr + (row0 ^ cstS)]        = tf32r(vb0[jj]);
                Bs[kr + ((row0 + 64) ^ cstS)] = tf32r(vb1[jj]);
            }
        }
        __syncthreads();
        if (k0 + 16 < Cv) {
            ra0 = *(const float4*)(Ap0 + k0 + 16);
            ra1 = *(const float4*)(Ap1 + k0 + 16);
            rb0 = *(const float4*)(Wp0 + k0 + 16);
            rb1 = *(const float4*)(Wp1 + k0 + 16);
        }
#pragma unroll
        for (int kk = 0; kk < 2; kk++) {
            const int kb = kk * 8;
            const int c0 = ((kb >> 2) & 3) << 3;          // k = kb+tig
            const int c1 = (((kb + 4) >> 2) & 3) << 3;    // k = kb+tig+4
            const int kr0 = (kb + tig) * 136;
            const int kr1 = (kb + tig + 4) * 136;
            unsigned a[4][4], bb[4][2];
#pragma unroll
            for (int mt = 0; mt < 4; mt++) {
                int m = wm + mt * 16 + gid;
                a[mt][0] = As[kr0 + (m ^ c0)];
                a[mt][1] = As[kr0 + ((m + 8) ^ c0)];
                a[mt][2] = As[kr1 + (m ^ c1)];
                a[mt][3] = As[kr1 + ((m + 8) ^ c1)];
            }
#pragma unroll
            for (int nt = 0; nt < 4; nt++) {
                int n = wn + nt * 8 + gid;
                bb[nt][0] = Bs[kr0 + (n ^ c0)];
                bb[nt][1] = Bs[kr1 + (n ^ c1)];
            }
#pragma unroll
            for (int mt = 0; mt < 4; mt++)
#pragma unroll
                for (int nt = 0; nt < 4; nt++)
                    mma8(acc[mt][nt], a[mt], bb[nt]);
        }
    }

#pragma unroll
    for (int mt = 0; mt < 4; mt++) {
        int r = m0 + wm + mt * 16 + gid;
#pragma unroll
        for (int nt = 0; nt < 4; nt++) {
            int c = n0 + wn + nt * 8 + tig * 2;
            float b0v = bias ? bias[c] : 0.0f;
            float b1v = bias ? bias[c + 1] : 0.0f;
            float2 v0, v1;
            v0.x = acc[mt][nt][0] + b0v;
            v0.y = acc[mt][nt][1] + b1v;
            v1.x = acc[mt][nt][2] + b0v;
            v1.y = acc[mt][nt][3] + b1v;
            *(float2*)(Cout + (size_t)r * Cv + c) = v0;
            *(float2*)(Cout + (size_t)(r + 8) * Cv + c) = v1;
        }
    }
}

// ---------------------------------------------------------------------------
// RoPE (in-place on q and k, token-major [Mrows,1024] layout).
// ---------------------------------------------------------------------------
__global__ __launch_bounds__(256) void rope_kernel(
    const float* __restrict__ fcos, const float* __restrict__ fsin)
{
    const long total = (long)Mrows * 512;
    long gid = (long)blockIdx.x * blockDim.x + threadIdx.x;
    if (gid >= 2 * total) return;
    float* arr = (gid < total) ? g_q : g_k;
    long id = (gid < total) ? gid : (gid - total);

    int m = (int)(id / 512);
    int p = (int)(id % 512);
    int col = p * 2;
    int d = col & 63;
    int s = m % TNv;

    float c0 = fcos[(size_t)s * HDv + d];
    float c1 = fcos[(size_t)s * HDv + d + 1];
    float s0 = fsin[(size_t)s * HDv + d];
    float s1 = fsin[(size_t)s * HDv + d + 1];

    float2 x = *(float2*)(arr + (size_t)m * Cv + col);
    float2 y;
    y.x = x.x * c0 - x.y * s0;
    y.y = x.y * c1 + x.x * s1;
    *(float2*)(arr + (size_t)m * Cv + col) = y;
}

// ---------------------------------------------------------------------------
// Flash attention with tf32 mma.
// Block = (b,h,t, 64-q-tile), 256 threads = 8 warps in 2(m) x 4(n) grid.
// Qs/Ks: [d][col] stride 72, swizzle col ^ (((d>>4)&3)<<3)   (CF ld+st)
// Vs:    [key][d] stride 72, plain
// Ps:    [key][q] stride 72, swizzle q ^ (((key>>4)&3)<<3)
// ---------------------------------------------------------------------------
#define QS_OFF 0
#define KS_OFF 4608
#define VS_OFF 9216
#define PS_OFF 13824
#define RED_OFF 18432
#define MR_OFF 18688
#define LR_OFF 18752
#define AR_OFF 18816
#define ATTN_SMEM_WORDS 18880

__global__ __launch_bounds__(256) void attn_mma()
{
    extern __shared__ unsigned usm[];
    unsigned* Qs = usm + QS_OFF;
    unsigned* Ks = usm + KS_OFF;
    unsigned* Vs = usm + VS_OFF;
    unsigned* Ps = usm + PS_OFF;
    float* red  = (float*)(usm + RED_OFF);   // [4][64]
    float* Mrow = (float*)(usm + MR_OFF);
    float* Lrow = (float*)(usm + LR_OFF);
    float* Arow = (float*)(usm + AR_OFF);

    const int bx = blockIdx.x;
    const int nb = bx % 9;
    const int tt = (bx / 9) % Tv;
    const int hh = (bx / (9 * Tv)) % Hv;
    const int b  = bx / (9 * Tv * Hv);
    const int tprev = (tt == 0) ? 1 : tt - 1;
    const int tnext = (tt == Tv - 1) ? Tv - 2 : tt + 1;

    const int t = threadIdx.x;
    const int lane = t & 31;
    const int w = t >> 5;
    const int gid = lane >> 2, tig = lane & 3;
    const int wm = w >> 2, wn = w & 3;
    const int lrow = t >> 2;           // loader row 0..63
    const int dc = (t & 3) * 16;
    const int cstL = (t & 3) << 3;     // ((d>>4)&3)<<3 for d = dc + 0..15

    // Q tile -> Qs[d][q], scaled by 1/sqrt(64), tf32-rounded
    {
        const float* qb =
            g_q + (size_t)(b * TNv + tt * Nv + nb * 64 + lrow) * Cv + hh * HDv + dc;
#pragma unroll
        for (int j = 0; j < 4; j++) {
            float4 v = *(const float4*)(qb + 4 * j);
            int d0 = dc + 4 * j;
            int cq = lrow ^ cstL;
            Qs[(d0 + 0) * 72 + cq] = tf32r(v.x * 0.125f);
            Qs[(d0 + 1) * 72 + cq] = tf32r(v.y * 0.125f);
            Qs[(d0 + 2) * 72 + cq] = tf32r(v.z * 0.125f);
            Qs[(d0 + 3) * 72 + cq] = tf32r(v.w * 0.125f);
        }
    }
    if (t < 64) { Mrow[t] = -1e30f; Lrow[t] = 0.0f; }

    float o[2][2][4];
#pragma unroll
    for (int mi = 0; mi < 2; mi++)
#pragma unroll
        for (int nj = 0; nj < 2; nj++)
#pragma unroll
            for (int r = 0; r < 4; r++) o[mi][nj][r] = 0.0f;

    for (int kt = 0; kt < 18; kt++) {
        const int tsrc = (kt < 9) ? tprev : tnext;
        const int nk0 = (kt % 9) * 64;
        const size_t tok = (size_t)(b * TNv + tsrc * Nv + nk0 + lrow);
        const float* kb_ = g_k + tok * Cv + hh * HDv + dc;
        const float* vb_ = g_v + tok * Cv + hh * HDv + dc;

        __syncthreads();
#pragma unroll
        for (int j = 0; j < 4; j++) {
            float4 kv = *(const float4*)(kb_ + 4 * j);
            float4 vv = *(const float4*)(vb_ + 4 * j);
            int d0 = dc + 4 * j;
            int ck = lrow ^ cstL;
            Ks[(d0 + 0) * 72 + ck] = tf32r(kv.x);
            Ks[(d0 + 1) * 72 + ck] = tf32r(kv.y);
            Ks[(d0 + 2) * 72 + ck] = tf32r(kv.z);
            Ks[(d0 + 3) * 72 + ck] = tf32r(kv.w);
            uint4 pv;
            pv.x = tf32r(vv.x); pv.y = tf32r(vv.y);
            pv.z = tf32r(vv.z); pv.w = tf32r(vv.w);
            *(uint4*)&Vs[lrow * 72 + d0] = pv;
        }
        __syncthreads();

        // S = Q @ K^T
        float s[2][2][4];
#pragma unroll
        for (int mi = 0; mi < 2; mi++)
#pragma unroll
            for (int ni = 0; ni < 2; ni++)
#pragma unroll
                for (int r = 0; r < 4; r++) s[mi][ni][r] = 0.0f;
#pragma unroll
        for (int kb = 0; kb < 64; kb += 8) {
            const int cs = ((kb >> 4) & 3) << 3;
            const int kr0 = (kb + tig) * 72;
            const int kr1 = (kb + tig + 4) * 72;
            unsigned a[2][4], bb[2][2];
#pragma unroll
            for (int mi = 0; mi < 2; mi++) {
                int q0 = wm * 32 + mi * 16 + gid;
                a[mi][0] = Qs[kr0 + (q0 ^ cs)];
                a[mi][1] = Qs[kr0 + ((q0 + 8) ^ cs)];
                a[mi][2] = Qs[kr1 + (q0 ^ cs)];
                a[mi][3] = Qs[kr1 + ((q0 + 8) ^ cs)];
            }
#pragma unroll
            for (int ni = 0; ni < 2; ni++) {
                int kc = wn * 16 + ni * 8 + gid;
                bb[ni][0] = Ks[kr0 + (kc ^ cs)];
                bb[ni][1] = Ks[kr1 + (kc ^ cs)];
            }
#pragma unroll
            for (int mi = 0; mi < 2; mi++)
#pragma unroll
                for (int ni = 0; ni < 2; ni++)
                    mma8(s[mi][ni], a[mi], bb[ni]);
        }

        // per-warp row max -> red[wn][row]
#pragma unroll
        for (int mi = 0; mi < 2; mi++)
#pragma unroll
            for (int h2 = 0; h2 < 2; h2++) {
                float mx = fmaxf(fmaxf(s[mi][0][h2 * 2], s[mi][0][h2 * 2 + 1]),
                                 fmaxf(s[mi][1][h2 * 2], s[mi][1][h2 * 2 + 1]));
                mx = fmaxf(mx, __shfl_xor_sync(0xffffffffu, mx, 1));
                mx = fmaxf(mx, __shfl_xor_sync(0xffffffffu, mx, 2));
                if (tig == 0)
                    red[wn * 64 + wm * 32 + mi * 16 + h2 * 8 + gid] = mx;
            }
        __syncthreads();
        if (t < 64) {
            float tm = fmaxf(fmaxf(red[t], red[64 + t]),
                             fmaxf(red[128 + t], red[192 + t]));
            float mold = Mrow[t];
            float mnew = fmaxf(mold, tm);
            Mrow[t] = mnew;
            Arow[t] = __expf(mold - mnew);
        }
        __syncthreads();

        // p = exp(s - m), stage P^T, row sums, rescale O
        const int cp = wn << 3;   // ((key>>4)&3)<<3, key in [wn*16, wn*16+16)
        const int k0c = wn * 16 + tig * 2;
#pragma unroll
        for (int mi = 0; mi < 2; mi++)
#pragma unroll
            for (int h2 = 0; h2 < 2; h2++) {
                int r = wm * 32 + mi * 16 + h2 * 8 + gid;
                float mrow = Mrow[r];
                float al = Arow[r];
                float p0 = __expf(s[mi][0][h2 * 2]     - mrow);
                float p1 = __expf(s[mi][0][h2 * 2 + 1] - mrow);
                float p2 = __expf(s[mi][1][h2 * 2]     - mrow);
                float p3 = __expf(s[mi][1][h2 * 2 + 1] - mrow);
                float rs = p0 + p1 + p2 + p3;
                rs += __shfl_xor_sync(0xffffffffu, rs, 1);
                rs += __shfl_xor_sync(0xffffffffu, rs, 2);
                if (tig == 0) red[wn * 64 + r] = rs;
                int rq = r ^ cp;
                Ps[(k0c + 0) * 72 + rq] = tf32r(p0);
                Ps[(k0c + 1) * 72 + rq] = tf32r(p1);
                Ps[(k0c + 8) * 72 + rq] = tf32r(p2);
                Ps[(k0c + 9) * 72 + rq] = tf32r(p3);
                o[mi][0][h2 * 2]     *= al;
                o[mi][0][h2 * 2 + 1] *= al;
                o[mi][1][h2 * 2]     *= al;
                o[mi][1][h2 * 2 + 1] *= al;
            }
        __syncthreads();
        if (t < 64)
            Lrow[t] = Lrow[t] * Arow[t] +
                      red[t] + red[64 + t] + red[128 + t] + red[192 + t];

        // O += P @ V
#pragma unroll
        for (int kb = 0; kb < 64; kb += 8) {
            const int cs = ((kb >> 4) & 3) << 3;
            const int kr0 = (kb + tig) * 72;
            const int kr1 = (kb + tig + 4) * 72;
            unsigned a[2][4], bb[2][2];
#pragma unroll
            for (int mi = 0; mi < 2; mi++) {
                int q0 = wm * 32 + mi * 16 + gid;
                a[mi][0] = Ps[kr0 + (q0 ^ cs)];
                a[mi][1] = Ps[kr0 + ((q0 + 8) ^ cs)];
                a[mi][2] = Ps[kr1 + (q0 ^ cs)];
                a[mi][3] = Ps[kr1 + ((q0 + 8) ^ cs)];
            }
#pragma unroll
            for (int nj = 0; nj < 2; nj++) {
                int dcol = wn * 16 + nj * 8 + gid;
                bb[nj][0] = Vs[kr0 + dcol];
                bb[nj][1] = Vs[kr1 + dcol];
            }
#pragma unroll
            for (int mi = 0; mi < 2; mi++)
#pragma unroll
                for (int nj = 0; nj < 2; nj++)
                    mma8(o[mi][nj], a[mi], bb[nj]);
        }
    }

    __syncthreads();
#pragma unroll
    for (int mi = 0; mi < 2; mi++)
#pragma unroll
        for (int h2 = 0; h2 < 2; h2++) {
            int r = wm * 32 + mi * 16 + h2 * 8 + gid;
            float inv = 1.0f / Lrow[r];
            size_t token = (size_t)(b * TNv + tt * Nv + nb * 64 + r);
            float* ob = g_o + token * Cv + hh * HDv;
#pragma unroll
            for (int nj = 0; nj < 2; nj++) {
                int dcol = wn * 16 + nj * 8 + tig * 2;
                float2 v2;
                v2.x = o[mi][nj][h2 * 2] * inv;
                v2.y = o[mi][nj][h2 * 2 + 1] * inv;
                *(float2*)(ob + dcol) = v2;
            }
        }
}

// ---------------------------------------------------------------------------
// Launch
// ---------------------------------------------------------------------------
extern "C" void kernel_launch(void* const* d_in, const int* in_sizes, int n_in,
                              void* d_out, int out_size)
{
    (void)in_sizes; (void)n_in; (void)out_size;
    const float* img  = (const float*)d_in[0];
    const float* fcos = (const float*)d_in[1];
    const float* fsin = (const float*)d_in[2];
    const float* Wq   = (const float*)d_in[3];
    const float* Wk   = (const float*)d_in[4];
    const float* Wv   = (const float*)d_in[5];
    const float* Wo   = (const float*)d_in[6];
    const float* bo   = (const float*)d_in[7];
    float* out = (float*)d_out;

    float *q, *k, *v, *o;
    cudaGetSymbolAddress((void**)&q, g_q);
    cudaGetSymbolAddress((void**)&k, g_k);
    cudaGetSymbolAddress((void**)&v, g_v);
    cudaGetSymbolAddress((void**)&o, g_o);

    cudaFuncSetAttribute(attn_mma,
                         cudaFuncAttributeMaxDynamicSharedMemorySize,
                         ATTN_SMEM_WORDS * (int)sizeof(unsigned));

    dim3 gblk(256);
    dim3 ggrid(Cv / 128, Mrows / 128);   // (8, 72)

    gemm_tf32<<<ggrid, gblk>>>(img, Wq, q, nullptr);
    gemm_tf32<<<ggrid, gblk>>>(img, Wk, k, nullptr);
    gemm_tf32<<<ggrid, gblk>>>(img, Wv, v, nullptr);

    long pairs2 = 2L * Mrows * 512;
    int rblocks = (int)((pairs2 + 255) / 256);
    rope_kernel<<<rblocks, 256>>>(fcos, fsin);

    attn_mma<<<Bv * Hv * Tv * 9, 256,
               ATTN_SMEM_WORDS * sizeof(unsigned)>>>();

    gemm_tf32<<<ggrid, gblk>>>(o, Wo, out, bo);
}